// round 3
// baseline (speedup 1.0000x reference)
#include <cuda_runtime.h>
#include <math.h>

// SenseEmbedding:
//  x:   [16384, 12] int32   (d_in[0])  -- [w0, w1, ctx0..ctx9]
//  W_g: [100000, 128] f32   (d_in[1])
//  W_s: [100000, 8, 128] f32 (d_in[2])
//  out: [16384, 1] f32
//
// One warp per row; lane l owns float4 slice [4l,4l+4) -> every row gather is
// one coalesced 512B access. W_s streamed evict-first (.cs) to keep W_g hot
// in L2. All 19 row-gathers per warp are independent and issued up front
// (64-reg budget) so DRAM latency is covered by MLP, and the post-argmax
// tail has no memory dependence (sense vecs stay in regs, target preloaded).

#define CTX 10
#define NUM_SENSES 8
#define VEC4 32  // 128 floats = 32 float4

__global__ void __launch_bounds__(256, 4)
sense_embedding_kernel(const int4* __restrict__ x4,
                       const float4* __restrict__ Wg,
                       const float4* __restrict__ Ws,
                       float* __restrict__ out,
                       int batch)
{
    int warp = (blockIdx.x * blockDim.x + threadIdx.x) >> 5;
    int lane = threadIdx.x & 31;
    if (warp >= batch) return;

    // x row = 12 ints = 3 x int4
    const int4* xr = x4 + (size_t)warp * 3;
    int4 xa = __ldg(&xr[0]);
    int4 xb = __ldg(&xr[1]);
    int4 xc = __ldg(&xr[2]);
    int w0 = xa.x, w1 = xa.y;
    int toks[CTX] = { xa.z, xa.w, xb.x, xb.y, xb.z, xb.w, xc.x, xc.y, xc.z, xc.w };

    // ---- issue ALL independent gathers up front (19 x LDG.128) ----
    float4 tv = __ldg(&Wg[(size_t)w1 * VEC4 + lane]);   // target row (tail dot)

    float4 c[CTX];
#pragma unroll
    for (int i = 0; i < CTX; i++)
        c[i] = __ldg(&Wg[(size_t)toks[i] * VEC4 + lane]);

    const float4* ws_row = Ws + (size_t)w0 * (NUM_SENSES * VEC4) + lane;
    float4 v[NUM_SENSES];
#pragma unroll
    for (int s = 0; s < NUM_SENSES; s++)
        v[s] = __ldcs(&ws_row[s * VEC4]);

    // ---- sum_context ----
    float4 acc = c[0];
#pragma unroll
    for (int i = 1; i < CTX; i++) {
        acc.x += c[i].x; acc.y += c[i].y; acc.z += c[i].z; acc.w += c[i].w;
    }

    // ---- per-lane partial dots ----
    float partial[NUM_SENSES];
#pragma unroll
    for (int s = 0; s < NUM_SENSES; s++)
        partial[s] = v[s].x * acc.x + v[s].y * acc.y
                   + v[s].z * acc.z + v[s].w * acc.w;

    // ---- warp-reduce each score; argmax (first max wins, like jnp.argmax) ----
    float best = -INFINITY;
    int bestk = 0;
#pragma unroll
    for (int s = 0; s < NUM_SENSES; s++) {
        float p = partial[s];
        p += __shfl_xor_sync(0xffffffffu, p, 16);
        p += __shfl_xor_sync(0xffffffffu, p, 8);
        p += __shfl_xor_sync(0xffffffffu, p, 4);
        p += __shfl_xor_sync(0xffffffffu, p, 2);
        p += __shfl_xor_sync(0xffffffffu, p, 1);
        if (p > best) { best = p; bestk = s; }  // warp-uniform
    }

    // ---- chosen sense is already in registers; select + final dot ----
    float4 ch = v[0];
#pragma unroll
    for (int s = 1; s < NUM_SENSES; s++)
        if (s == bestk) ch = v[s];

    float d = ch.x * tv.x + ch.y * tv.y + ch.z * tv.z + ch.w * tv.w;
    d += __shfl_xor_sync(0xffffffffu, d, 16);
    d += __shfl_xor_sync(0xffffffffu, d, 8);
    d += __shfl_xor_sync(0xffffffffu, d, 4);
    d += __shfl_xor_sync(0xffffffffu, d, 2);
    d += __shfl_xor_sync(0xffffffffu, d, 1);

    if (lane == 0)
        out[warp] = 1.0f / (1.0f + __expf(-d));
}

extern "C" void kernel_launch(void* const* d_in, const int* in_sizes, int n_in,
                              void* d_out, int out_size)
{
    const int4*   x  = (const int4*)d_in[0];
    const float4* Wg = (const float4*)d_in[1];
    const float4* Ws = (const float4*)d_in[2];
    float* out = (float*)d_out;

    int batch = in_sizes[0] / (2 + CTX);   // 16384
    int threads = 256;                      // 8 warps/block
    int blocks = (batch * 32 + threads - 1) / threads;
    sense_embedding_kernel<<<blocks, threads>>>(x, Wg, Ws, out, batch);
}